// round 10
// baseline (speedup 1.0000x reference)
#include <cuda_runtime.h>
#include <float.h>

// Problem constants (fixed shapes)
#define NG    128
#define NPG   64
#define EPG   1024
#define ETOT  131072
#define HD    128
#define FD    384      // 3*H
#define KSEL  32
#define DOUT  10
#define NT    512      // 16 warps

// strides (floats)
#define SA    68       // adjacency row stride (symmetric: A[j*SA+r] == A[r][j])
#define SFT   68       // featsT / xsT row stride (row = feature channel, cols = 64 nodes)
#define STD   260      // duplicated rows (tmpdup / Wcdup): 256 data + 4 pad

// Shared memory layout (float indices)
#define OFF_A      0                        // 64*68   = 4352
#define OFF_FEATST 4352                     // 384*68  = 26112  (h1 rows 0..127, h2 128..255, h3 256..383)
#define OFF_XST    (OFF_FEATST + 256*SFT)   // xsT[128][68] aliases h3 rows (dead before h3 written)
#define OFF_TMPD   30464                    // 64*260  = 16640  (duplicated XW result)
#define OFF_WC     47104                    // 32*260  = 8320   (duplicated W chunk; reused as psum)
#define OFF_SCORE  55424                    // 64
#define OFF_TVEC   55488                    // 64
#define OFF_SLIST  55552                    // 32 (int)
#define OFF_SCNT   55584                    // 4
#define OFF_RD     55588                    // 768
#define OFF_T1     56356                    // 128
#define OFF_T2     56484                    // 64
#define OFF_WAS    56548                    // 384
#define SMEM_FLOATS 56932                   // 227728 bytes

typedef unsigned long long ull;

// packed fp32 pair FMA: acc.lo += a.lo*b.lo ; acc.hi += a.hi*b.hi
__device__ __forceinline__ void ffma2(ull& acc, ull a, ull b)
{
    asm("fma.rn.f32x2 %0, %1, %2, %0;" : "+l"(acc) : "l"(a), "l"(b));
}
__device__ __forceinline__ float2 u2f(ull v)
{
    float2 f;
    asm("mov.b64 {%0, %1}, %2;" : "=f"(f.x), "=f"(f.y) : "l"(v));
    return f;
}

// prefetch one FULL 32-row chunk of a 128x128 W into registers:
// 32*128 floats = 2048 float2 -> 4 float2 per thread (512 threads)
__device__ __forceinline__ void ldg_chunk(const float* __restrict__ Wg, int kc,
                                          float2* pf, int tid)
{
    const float2* s = (const float2*)(Wg + kc * HD);
#pragma unroll
    for (int h = 0; h < 4; ++h) pf[h] = s[h * NT + tid];
}

// store chunk duplicated: Wc[k][2c] = Wc[k][2c+1] = W[kc+k][c]  (16B stores)
__device__ __forceinline__ void sts_dup(float* __restrict__ Wc, const float2* pf, int tid)
{
#pragma unroll
    for (int h = 0; h < 4; ++h) {
        int i  = h * NT + tid;   // float2 index within 32x128 chunk (0..2047)
        int k  = i >> 6;         // 0..31
        int f2 = i & 63;         // float2 index within row
        float2 v = pf[h];
        *(float4*)(Wc + k * STD + f2 * 4) = make_float4(v.x, v.x, v.y, v.y);
    }
}

// ---------------------------------------------------------------------------
// tmpd (duplicated) = In @ W.  InT[k][r] transposed in smem, W staged duplicated.
// Thread: rows r0..r0+3 (two packed pairs), cols c0..c0+3.
// Per k: 1 LDS.128 (row quad), 2 LDS.128 (dup W), 8 FFMA2. No packing movs.
// ---------------------------------------------------------------------------
__device__ __forceinline__ void gemm_xw(const float* __restrict__ InT,
                                        const float* __restrict__ Wg,
                                        float* __restrict__ Wc,
                                        float* __restrict__ tmpd,
                                        int tid, int r0, int c0, float2* pf)
{
    ull acc[2][4];
#pragma unroll
    for (int p = 0; p < 2; ++p)
#pragma unroll
        for (int c = 0; c < 4; ++c) acc[p][c] = 0ull;

    for (int kc = 0; kc < 128; kc += 32) {
        __syncthreads();                 // previous chunk consumers done
        sts_dup(Wc, pf, tid);
        if (kc < 96) ldg_chunk(Wg, kc + 32, pf, tid);  // overlap with compute
        __syncthreads();
#pragma unroll 4
        for (int k = 0; k < 32; ++k) {
            ulonglong2 av = *(const ulonglong2*)(InT + (kc + k) * SFT + r0);
            ulonglong2 w0 = *(const ulonglong2*)(Wc + k * STD + c0 * 2);
            ulonglong2 w1 = *(const ulonglong2*)(Wc + k * STD + c0 * 2 + 4);
            ffma2(acc[0][0], av.x, w0.x);
            ffma2(acc[0][1], av.x, w0.y);
            ffma2(acc[0][2], av.x, w1.x);
            ffma2(acc[0][3], av.x, w1.y);
            ffma2(acc[1][0], av.y, w0.x);
            ffma2(acc[1][1], av.y, w0.y);
            ffma2(acc[1][2], av.y, w1.x);
            ffma2(acc[1][3], av.y, w1.y);
        }
    }
    // store result duplicated for the A-mult stage
#pragma unroll
    for (int p = 0; p < 2; ++p)
#pragma unroll
        for (int cj = 0; cj < 4; ++cj) {
            float2 f = u2f(acc[p][cj]);
            float* d = tmpd + (r0 + 2 * p) * STD + (c0 + cj) * 2;
            *(float2*)(d)       = make_float2(f.x, f.x);
            *(float2*)(d + STD) = make_float2(f.y, f.y);
        }
}

// ---------------------------------------------------------------------------
// fT[c][r] = relu((A @ tmp)[r][c] + b[c]).  A symmetric: row pairs natural.
// Optionally prefetches next layer's W chunk 0 into pf (overlaps with compute).
// ---------------------------------------------------------------------------
__device__ __forceinline__ void amult_relu(const float* __restrict__ A,
                                           const float* __restrict__ tmpd,
                                           const float* __restrict__ bvec,
                                           float* __restrict__ fT,
                                           int r0, int c0,
                                           const float* __restrict__ Wnext,
                                           float2* pf, int tid)
{
    __syncthreads();                     // tmpd stores visible
    if (Wnext) ldg_chunk(Wnext, 0, pf, tid);
    ull acc[2][4];
#pragma unroll
    for (int p = 0; p < 2; ++p)
#pragma unroll
        for (int c = 0; c < 4; ++c) acc[p][c] = 0ull;
#pragma unroll 4
    for (int k = 0; k < 64; ++k) {
        ulonglong2 av = *(const ulonglong2*)(A + k * SA + r0);   // (A[r0][k],A[r0+1][k]),... by symmetry
        ulonglong2 t0 = *(const ulonglong2*)(tmpd + k * STD + c0 * 2);
        ulonglong2 t1 = *(const ulonglong2*)(tmpd + k * STD + c0 * 2 + 4);
        ffma2(acc[0][0], av.x, t0.x);
        ffma2(acc[0][1], av.x, t0.y);
        ffma2(acc[0][2], av.x, t1.x);
        ffma2(acc[0][3], av.x, t1.y);
        ffma2(acc[1][0], av.y, t0.x);
        ffma2(acc[1][1], av.y, t0.y);
        ffma2(acc[1][2], av.y, t1.x);
        ffma2(acc[1][3], av.y, t1.y);
    }
    float4 bb = *(const float4*)(bvec + c0);
    float bba[4] = {bb.x, bb.y, bb.z, bb.w};
#pragma unroll
    for (int p = 0; p < 2; ++p)
#pragma unroll
        for (int cj = 0; cj < 4; ++cj) {
            float2 f = u2f(acc[p][cj]);
            float2 v = make_float2(fmaxf(f.x + bba[cj], 0.f),
                                   fmaxf(f.y + bba[cj], 0.f));
            *(float2*)(fT + (c0 + cj) * SFT + r0 + 2 * p) = v;
        }
    __syncthreads();
}

__global__ void __launch_bounds__(NT, 1)
sagpool_kernel(const float* __restrict__ x, const int* __restrict__ ei,
               const float* __restrict__ W1, const float* __restrict__ b1,
               const float* __restrict__ W2, const float* __restrict__ b2,
               const float* __restrict__ W3, const float* __restrict__ b3,
               const float* __restrict__ Wa, const float* __restrict__ ba,
               const float* __restrict__ M1, const float* __restrict__ c1,
               const float* __restrict__ M2, const float* __restrict__ c2,
               const float* __restrict__ M3, const float* __restrict__ c3,
               float* __restrict__ out)
{
    extern __shared__ float sm[];
    float* A      = sm + OFF_A;
    float* featsT = sm + OFF_FEATST;
    float* xsT    = sm + OFF_XST;
    float* tmpd   = sm + OFF_TMPD;
    float* Wc     = sm + OFF_WC;
    float* score  = sm + OFF_SCORE;
    float* tvec   = sm + OFF_TVEC;
    int*   slist  = (int*)(sm + OFF_SLIST);
    int*   scnt   = (int*)(sm + OFF_SCNT);
    float* rdout  = sm + OFF_RD;
    float* t1     = sm + OFF_T1;
    float* t2     = sm + OFF_T2;
    float* was    = sm + OFF_WAS;

    const int g    = blockIdx.x;
    const int tid  = threadIdx.x;
    const int w    = tid >> 5;
    const int lane = tid & 31;
    const int r0   = (w & 3) * 16 + (lane & 3) * 4;   // 4 rows (2 packed pairs)
    const int c0   = (w >> 2) * 32 + (lane >> 2) * 4; // 4 cols
    const int base = g * NPG;
    const int row8 = tid >> 3;
    const int l8   = tid & 7;

    // ---- early LDGs: W1 chunk0 + edge list (latency overlapped with A build) ----
    float2 pf[4];
    ldg_chunk(W1, 0, pf, tid);
    const int* es = ei + g * EPG;
    const int* ed = ei + ETOT + g * EPG;
    int e_s0 = es[tid], e_s1 = es[tid + NT];
    int e_d0 = ed[tid], e_d1 = ed[tid + NT];

    for (int i = tid; i < NPG * SA; i += NT) A[i] = 0.f;
    if (tid == 0) *scnt = 0;
    __syncthreads();
    {   // scatter (symmetric writes)
        int s0 = e_s0 - base, d0v = e_d0 - base;
        int s1 = e_s1 - base, d1v = e_d1 - base;
        A[s0 * SA + d0v] = 1.f; A[d0v * SA + s0] = 1.f;
        A[s1 * SA + d1v] = 1.f; A[d1v * SA + s1] = 1.f;
    }
    __syncthreads();
    if (tid < 64) A[tid * SA + tid] += 1.f;  // A += I (diag may reach 2)
    // x transposed into xsT[k][r] (ordered before use by gemm's internal barriers)
    {
        float4 xv[4];
#pragma unroll
        for (int it = 0; it < 4; ++it) {
            int i = it * NT + tid;
            int r = i & 63, k4 = i >> 6;
            xv[it] = *(const float4*)(x + (base + r) * HD + k4 * 4);
        }
#pragma unroll
        for (int it = 0; it < 4; ++it) {
            int i = it * NT + tid;
            int r = i & 63, k4 = i >> 6;
            xsT[(4 * k4 + 0) * SFT + r] = xv[it].x;
            xsT[(4 * k4 + 1) * SFT + r] = xv[it].y;
            xsT[(4 * k4 + 2) * SFT + r] = xv[it].z;
            xsT[(4 * k4 + 3) * SFT + r] = xv[it].w;
        }
    }
    if (tid < FD) was[tid] = Wa[tid];
    __syncthreads();
    {   // rowsum -> dinv
        float s = 0.f;
#pragma unroll
        for (int k = l8; k < 64; k += 8) s += A[row8 * SA + k];
        s += __shfl_xor_sync(0xFFFFFFFFu, s, 1);
        s += __shfl_xor_sync(0xFFFFFFFFu, s, 2);
        s += __shfl_xor_sync(0xFFFFFFFFu, s, 4);
        if (l8 == 0) tvec[row8] = rsqrtf(s);
    }
    __syncthreads();
    for (int i = tid; i < NPG * NPG; i += NT) {
        int r = i >> 6, c = i & 63;
        A[r * SA + c] *= tvec[r] * tvec[c];   // stays symmetric
    }

    // ---- 3 GCN layers: hT = relu(A @ (In @ W) + b), all f32x2 natural pairs ----
    gemm_xw(xsT, W1, Wc, tmpd, tid, r0, c0, pf);
    amult_relu(A, tmpd, b1, featsT + 0 * SFT,   r0, c0, W2, pf, tid);
    gemm_xw(featsT + 0 * SFT,   W2, Wc, tmpd, tid, r0, c0, pf);
    amult_relu(A, tmpd, b2, featsT + 128 * SFT, r0, c0, W3, pf, tid);
    gemm_xw(featsT + 128 * SFT, W3, Wc, tmpd, tid, r0, c0, pf);
    amult_relu(A, tmpd, b3, featsT + 256 * SFT, r0, c0, (const float*)0, pf, tid);

    // ---- attention: score = tanh(A @ (feats @ Wa) + ba) ----
    {
        float p = 0.f;
#pragma unroll 4
        for (int c = l8; c < FD; c += 8) p = fmaf(featsT[c * SFT + row8], was[c], p);
        p += __shfl_xor_sync(0xFFFFFFFFu, p, 1);
        p += __shfl_xor_sync(0xFFFFFFFFu, p, 2);
        p += __shfl_xor_sync(0xFFFFFFFFu, p, 4);
        if (l8 == 0) tvec[row8] = p;
    }
    __syncthreads();
    {
        float s = 0.f;
#pragma unroll
        for (int k = l8; k < 64; k += 8) s = fmaf(A[row8 * SA + k], tvec[k], s);
        s += __shfl_xor_sync(0xFFFFFFFFu, s, 1);
        s += __shfl_xor_sync(0xFFFFFFFFu, s, 2);
        s += __shfl_xor_sync(0xFFFFFFFFu, s, 4);
        if (l8 == 0) score[row8] = tanhf(s + ba[0]);
    }
    __syncthreads();
    // ---- top-K (jax tie-break: smaller index wins among equals) ----
    if (tid < 64) {
        float si = score[tid];
        int rank = 0;
#pragma unroll
        for (int j = 0; j < 64; ++j) {
            float sj = score[j];
            rank += (sj > si) || (sj == si && j < tid);
        }
        if (rank < KSEL) {
            int p = atomicAdd(scnt, 1);
            slist[p] = tid;   // unordered OK: mean & max order-invariant
        }
    }
    __syncthreads();
    // ---- readout: mean || max of feats*score over selected (per channel) ----
    if (tid < FD) {
        float ssum = 0.f, mx = -FLT_MAX;
#pragma unroll
        for (int j = 0; j < KSEL; ++j) {
            int i = slist[j];
            float v = featsT[tid * SFT + i] * score[i];
            ssum += v;
            mx = fmaxf(mx, v);
        }
        rdout[tid]      = ssum * (1.f / (float)KSEL);
        rdout[FD + tid] = mx;
    }
    __syncthreads();
    // ---- MLP layer 1: [768] -> [128] ----
    {
        float* psum = Wc;
        int j = tid & 127, q = tid >> 7;
        float a = 0.f;
#pragma unroll 8
        for (int c = q * 192; c < q * 192 + 192; ++c)
            a = fmaf(rdout[c], M1[c * HD + j], a);
        psum[tid] = a;
        __syncthreads();
        if (tid < 128)
            t1[tid] = fmaxf(psum[tid] + psum[tid + 128] + psum[tid + 256] + psum[tid + 384] + c1[tid], 0.f);
    }
    __syncthreads();
    // ---- MLP layer 2: [128] -> [64] ----
    {
        float* psum = Wc;
        int j = tid & 63, q = tid >> 6;
        float a = 0.f;
#pragma unroll
        for (int c = q * 16; c < q * 16 + 16; ++c)
            a = fmaf(t1[c], M2[c * 64 + j], a);
        psum[tid] = a;
        __syncthreads();
        if (tid < 64) {
            float s = c2[tid];
#pragma unroll
            for (int q2 = 0; q2 < 8; ++q2) s += psum[tid + q2 * 64];
            t2[tid] = fmaxf(s, 0.f);
        }
    }
    __syncthreads();
    // ---- MLP layer 3: [64] -> [10] ----
    if (tid < DOUT) {
        float a = c3[tid];
#pragma unroll
        for (int c = 0; c < 64; ++c) a = fmaf(t2[c], M3[c * DOUT + tid], a);
        out[g * DOUT + tid] = a;
    }
}

extern "C" void kernel_launch(void* const* d_in, const int* in_sizes, int n_in,
                              void* d_out, int out_size)
{
    const float* x  = (const float*)d_in[0];
    const int*   ei = (const int*)d_in[1];
    // d_in[2] = batch (unused: graphs are contiguous 64-node blocks)
    const float* W1 = (const float*)d_in[3];
    const float* b1 = (const float*)d_in[4];
    const float* W2 = (const float*)d_in[5];
    const float* b2 = (const float*)d_in[6];
    const float* W3 = (const float*)d_in[7];
    const float* b3 = (const float*)d_in[8];
    const float* Wa = (const float*)d_in[9];
    const float* ba = (const float*)d_in[10];
    const float* M1 = (const float*)d_in[11];
    const float* c1 = (const float*)d_in[12];
    const float* M2 = (const float*)d_in[13];
    const float* c2 = (const float*)d_in[14];
    const float* M3 = (const float*)d_in[15];
    const float* c3 = (const float*)d_in[16];
    float* out = (float*)d_out;

    const int smem_bytes = SMEM_FLOATS * (int)sizeof(float);
    cudaFuncSetAttribute(sagpool_kernel,
                         cudaFuncAttributeMaxDynamicSharedMemorySize, smem_bytes);
    sagpool_kernel<<<NG, NT, smem_bytes>>>(x, ei, W1, b1, W2, b2, W3, b3,
                                           Wa, ba, M1, c1, M2, c2, M3, c3, out);
}

// round 12
// speedup vs baseline: 1.2212x; 1.2212x over previous
#include <cuda_runtime.h>
#include <cuda_bf16.h>
#include <stdint.h>
#include <float.h>

// Problem constants
#define NG    128
#define NPG   64
#define EPG   1024
#define ETOT  131072
#define HD    128
#define FD    384
#define KSEL  32
#define DOUT  10
#define NT    256      // 8 warps

typedef uint32_t u32;

// ---- smem byte layout ----
// bf16 buffers use row stride 144B (72 bf16): 16B-aligned rows, banks 4r mod 32 -> ldmatrix conflict-free
#define SB2     144
#define FT_LO   18432          // lo half offset within a feature buffer (128 rows x 144B)
#define OFF_FT0 0              // h1 (hi+lo)   36864B
#define OFF_FT1 36864          // h2
#define OFF_FT2 73728          // x, then h3 (x dead after layer 1)
#define OFF_ABF 110592         // A_adj bf16 hi (64x144B); lo at +9216
#define ABF_LO  9216
#define OFF_WT  129024         // W^T k-chunk hi (128x144B); lo at +18432
#define WT_LO   18432
#define OFF_AFB 165888         // fp32 A 64x68
#define SAF     68
// fp32 misc (float indices into sm[])
#define FI_AF    41472
#define FI_SCORE 45824
#define FI_SDOT  45888
#define FI_TVEC  45952
#define FI_SLIST 46016
#define FI_SCNT  46048
#define FI_RD    46052
#define FI_T1    46820
#define FI_T2    46948
#define FI_WAS   47012
#define FI_BS    47396
#define FI_PSUM  47524
#define SMEM_BYTES 191168

static __device__ __forceinline__ u32 smem_u32(const void* p)
{
    u32 a;
    asm("{ .reg .u64 t; cvta.to.shared.u64 t, %1; cvt.u32.u64 %0, t; }" : "=r"(a) : "l"(p));
    return a;
}

static __device__ __forceinline__ void ldm_x4(u32& r0, u32& r1, u32& r2, u32& r3, u32 addr)
{
    asm volatile("ldmatrix.sync.aligned.m8n8.x4.shared.b16 {%0,%1,%2,%3}, [%4];"
                 : "=r"(r0), "=r"(r1), "=r"(r2), "=r"(r3) : "r"(addr));
}
static __device__ __forceinline__ void ldm_x2(u32& r0, u32& r1, u32 addr)
{
    asm volatile("ldmatrix.sync.aligned.m8n8.x2.shared.b16 {%0,%1}, [%2];"
                 : "=r"(r0), "=r"(r1) : "r"(addr));
}
static __device__ __forceinline__ void ldm_x2t(u32& r0, u32& r1, u32 addr)
{
    asm volatile("ldmatrix.sync.aligned.m8n8.x2.trans.shared.b16 {%0,%1}, [%2];"
                 : "=r"(r0), "=r"(r1) : "r"(addr));
}
static __device__ __forceinline__ void mma_bf16(float* d, u32 a0, u32 a1, u32 a2, u32 a3,
                                                u32 b0, u32 b1)
{
    asm volatile("mma.sync.aligned.m16n8k16.row.col.f32.bf16.bf16.f32 "
                 "{%0,%1,%2,%3}, {%4,%5,%6,%7}, {%8,%9}, {%0,%1,%2,%3};"
                 : "+f"(d[0]), "+f"(d[1]), "+f"(d[2]), "+f"(d[3])
                 : "r"(a0), "r"(a1), "r"(a2), "r"(a3), "r"(b0), "r"(b1));
}
static __device__ __forceinline__ void bsplit(float v, __nv_bfloat16& h, __nv_bfloat16& l)
{
    h = __float2bfloat16_rn(v);
    l = __float2bfloat16_rn(v - __bfloat162float(h));
}
static __device__ __forceinline__ u32 bpack(__nv_bfloat16 a, __nv_bfloat16 b)
{
    return (u32)__bfloat16_as_ushort(a) | ((u32)__bfloat16_as_ushort(b) << 16);
}

__global__ void __launch_bounds__(NT, 1)
sagpool_mma_kernel(const float* __restrict__ x, const int* __restrict__ ei,
                   const float* __restrict__ W1, const float* __restrict__ b1,
                   const float* __restrict__ W2, const float* __restrict__ b2,
                   const float* __restrict__ W3, const float* __restrict__ b3,
                   const float* __restrict__ Wa, const float* __restrict__ ba,
                   const float* __restrict__ M1, const float* __restrict__ c1,
                   const float* __restrict__ M2, const float* __restrict__ c2,
                   const float* __restrict__ M3, const float* __restrict__ c3,
                   float* __restrict__ out)
{
    extern __shared__ float sm[];
    char* smc = (char*)sm;
    float* Af    = sm + FI_AF;
    float* score = sm + FI_SCORE;
    float* sdot  = sm + FI_SDOT;
    float* tvec  = sm + FI_TVEC;
    int*   slist = (int*)(sm + FI_SLIST);
    int*   scnt  = (int*)(sm + FI_SCNT);
    float* rd    = sm + FI_RD;
    float* t1    = sm + FI_T1;
    float* t2    = sm + FI_T2;
    float* wasf  = sm + FI_WAS;
    float* bsf   = sm + FI_BS;
    float* psum  = sm + FI_PSUM;

    const int g    = blockIdx.x;
    const int tid  = threadIdx.x;
    const int wid  = tid >> 5;
    const int lane = tid & 31;
    const int gq   = lane >> 2;   // mma group row
    const int tq   = lane & 3;    // mma group col
    const int base = g * NPG;
    const u32 sbu  = smem_u32(sm);
    const int f0   = wid * 16;    // warp's f-strip

    // ---- build fp32 adjacency ----
    for (int i = tid; i < NPG * SAF; i += NT) Af[i] = 0.f;
    if (tid == 0) *scnt = 0;
    __syncthreads();
    {
        const int* es = ei + g * EPG;
        const int* ed = ei + ETOT + g * EPG;
#pragma unroll
        for (int e = tid; e < EPG; e += NT) {
            int s = es[e] - base, d = ed[e] - base;
            Af[s * SAF + d] = 1.f;
            Af[d * SAF + s] = 1.f;
        }
    }
    __syncthreads();
    if (tid < 64) Af[tid * SAF + tid] += 1.f;  // A += I (diag may reach 2)
    __syncthreads();
    {   // rowsum -> dinv (4 threads/row)
        int r4 = tid >> 2, l4 = tid & 3;
        float s = 0.f;
        for (int k = l4; k < 64; k += 4) s += Af[r4 * SAF + k];
        s += __shfl_xor_sync(0xFFFFFFFFu, s, 1);
        s += __shfl_xor_sync(0xFFFFFFFFu, s, 2);
        if (l4 == 0) tvec[r4] = rsqrtf(s);
    }
    __syncthreads();
    for (int i = tid; i < NPG * NPG; i += NT) {
        int r = i >> 6, c = i & 63;
        Af[r * SAF + c] *= tvec[r] * tvec[c];   // symmetric
    }
    if (tid < FD) { wasf[tid] = Wa[tid]; if (tid + NT < FD) wasf[tid + NT] = Wa[tid + NT]; }
    __syncthreads();
    // A_adj bf16 hi/lo  (BT[n=m][k=j] = A[m][j], row stride 144B)
#pragma unroll
    for (int it = 0; it < 16; ++it) {
        int idx = it * NT + tid;       // 64 m x 64 j
        int m = idx >> 6, j = idx & 63;
        __nv_bfloat16 h, l;
        bsplit(Af[m * SAF + j], h, l);
        *(__nv_bfloat16*)(smc + OFF_ABF + m * SB2 + j * 2)          = h;
        *(__nv_bfloat16*)(smc + OFF_ABF + ABF_LO + m * SB2 + j * 2) = l;
    }
    // x -> xT[k][m] bf16 hi/lo into FT2
#pragma unroll
    for (int it = 0; it < 8; ++it) {
        int idx = it * NT + tid;       // 64 m x 32 k-quads
        int m = idx >> 5, kq = idx & 31;
        float4 v = *(const float4*)(x + (base + m) * HD + 4 * kq);
        float va[4] = {v.x, v.y, v.z, v.w};
#pragma unroll
        for (int e = 0; e < 4; ++e) {
            __nv_bfloat16 h, l;
            bsplit(va[e], h, l);
            int k = 4 * kq + e;
            *(__nv_bfloat16*)(smc + OFF_FT2 + k * SB2 + m * 2)         = h;
            *(__nv_bfloat16*)(smc + OFF_FT2 + FT_LO + k * SB2 + m * 2) = l;
        }
    }

    const int inOff[3]  = {OFF_FT2, OFF_FT0, OFF_FT1};
    const int outOff[3] = {OFF_FT0, OFF_FT1, OFF_FT2};
    const float* WgL[3] = {W1, W2, W3};
    const float* bgL[3] = {b1, b2, b3};
    const u32 wtH  = sbu + OFF_WT;
    const u32 abfH = sbu + OFF_ABF;

#pragma unroll 1
    for (int L = 0; L < 3; ++L) {
        const float* Wg = WgL[L];
        const u32 inH   = sbu + inOff[L];
        const int outB  = outOff[L];
        if (tid < HD) bsf[tid] = bgL[L][tid];

        float dA[8][4];
#pragma unroll
        for (int j = 0; j < 8; ++j)
#pragma unroll
            for (int q = 0; q < 4; ++q) dA[j][q] = 0.f;

        // GEMM1: tmpT[f][m] = W^T[f][k] @ In^T (B = InT via trans-ldmatrix), k=128
        for (int ck = 0; ck < 2; ++ck) {
            __syncthreads();  // prior chunk consumers done (also orders fT/bsf writes)
            // stage W^T chunk (rows f=128, cols kk=0..63), hi/lo
#pragma unroll
            for (int it = 0; it < 16; ++it) {
                int idx = it * NT + tid;   // 64 k x 64 f-pairs
                int k = idx >> 6, f2 = idx & 63;
                float2 v = *(const float2*)(Wg + (ck * 64 + k) * HD + 2 * f2);
                __nv_bfloat16 h0, l0, h1, l1;
                bsplit(v.x, h0, l0); bsplit(v.y, h1, l1);
                *(__nv_bfloat16*)(smc + OFF_WT + (2 * f2) * SB2 + k * 2)             = h0;
                *(__nv_bfloat16*)(smc + OFF_WT + (2 * f2 + 1) * SB2 + k * 2)         = h1;
                *(__nv_bfloat16*)(smc + OFF_WT + WT_LO + (2 * f2) * SB2 + k * 2)     = l0;
                *(__nv_bfloat16*)(smc + OFF_WT + WT_LO + (2 * f2 + 1) * SB2 + k * 2) = l1;
            }
            __syncthreads();
#pragma unroll
            for (int s = 0; s < 4; ++s) {
                u32 aadr = wtH + (u32)((f0 + (lane & 15)) * SB2 + (s * 16 + (lane >> 4) * 8) * 2);
                u32 ah0, ah1, ah2, ah3, al0, al1, al2, al3;
                ldm_x4(ah0, ah1, ah2, ah3, aadr);
                ldm_x4(al0, al1, al2, al3, aadr + WT_LO);
                int kg = ck * 64 + s * 16;
                u32 badr = inH + (u32)((kg + (lane & 15)) * SB2);
#pragma unroll
                for (int j = 0; j < 8; ++j) {
                    u32 bh0, bh1, bl0, bl1;
                    ldm_x2t(bh0, bh1, badr + j * 16);
                    ldm_x2t(bl0, bl1, badr + FT_LO + j * 16);
                    mma_bf16(dA[j], ah0, ah1, ah2, ah3, bh0, bh1);
                    mma_bf16(dA[j], ah0, ah1, ah2, ah3, bl0, bl1);
                    mma_bf16(dA[j], al0, al1, al2, al3, bh0, bh1);
                }
            }
        }
        // GEMM2 A-fragments (tmpT) directly from D1 registers: bf16 hi/lo split in-register
        u32 a2h[4][4], a2l[4][4];
#pragma unroll
        for (int s = 0; s < 4; ++s)
#pragma unroll
            for (int q = 0; q < 2; ++q) {
                __nv_bfloat16 h0, l0, h1, l1;
                bsplit(dA[2 * s][2 * q], h0, l0);
                bsplit(dA[2 * s][2 * q + 1], h1, l1);
                a2h[s][q] = bpack(h0, h1);
                a2l[s][q] = bpack(l0, l1);
                bsplit(dA[2 * s + 1][2 * q], h0, l0);
                bsplit(dA[2 * s + 1][2 * q + 1], h1, l1);
                a2h[s][2 + q] = bpack(h0, h1);
                a2l[s][2 + q] = bpack(l0, l1);
            }
        // GEMM2: hT[f][m] = tmpT[f][j] @ A_adj (B = A_adj rows, symmetric), k=64
        float dB[8][4];
#pragma unroll
        for (int n = 0; n < 8; ++n)
#pragma unroll
            for (int q = 0; q < 4; ++q) dB[n][q] = 0.f;
#pragma unroll
        for (int s = 0; s < 4; ++s)
#pragma unroll
            for (int n = 0; n < 8; ++n) {
                u32 ba = abfH + (u32)((n * 8 + (lane & 7)) * SB2 + (s * 16 + ((lane >> 3) & 1) * 8) * 2);
                u32 bh0, bh1, bl0, bl1;
                ldm_x2(bh0, bh1, ba);
                ldm_x2(bl0, bl1, ba + ABF_LO);
                mma_bf16(dB[n], a2h[s][0], a2h[s][1], a2h[s][2], a2h[s][3], bh0, bh1);
                mma_bf16(dB[n], a2h[s][0], a2h[s][1], a2h[s][2], a2h[s][3], bl0, bl1);
                mma_bf16(dB[n], a2l[s][0], a2l[s][1], a2l[s][2], a2l[s][3], bh0, bh1);
            }
        // epilogue: h = relu(D2 + b[f]); store hT hi/lo bf16
        {
            float b0v = bsf[f0 + gq], b1v = bsf[f0 + 8 + gq];
#pragma unroll
            for (int n = 0; n < 8; ++n) {
                int m0 = n * 8 + 2 * tq;
                float v00 = fmaxf(dB[n][0] + b0v, 0.f);
                float v01 = fmaxf(dB[n][1] + b0v, 0.f);
                float v10 = fmaxf(dB[n][2] + b1v, 0.f);
                float v11 = fmaxf(dB[n][3] + b1v, 0.f);
                __nv_bfloat16 h0, l0, h1, l1;
                bsplit(v00, h0, l0); bsplit(v01, h1, l1);
                *(u32*)(smc + outB + (f0 + gq) * SB2 + m0 * 2)         = bpack(h0, h1);
                *(u32*)(smc + outB + FT_LO + (f0 + gq) * SB2 + m0 * 2) = bpack(l0, l1);
                bsplit(v10, h0, l0); bsplit(v11, h1, l1);
                *(u32*)(smc + outB + (f0 + 8 + gq) * SB2 + m0 * 2)         = bpack(h0, h1);
                *(u32*)(smc + outB + FT_LO + (f0 + 8 + gq) * SB2 + m0 * 2) = bpack(l0, l1);
            }
        }
    }
    __syncthreads();

    const int ftOff[3] = {OFF_FT0, OFF_FT1, OFF_FT2};
    // ---- sdot[m] = sum_f feats[m][f]*Wa[f]  (4 threads per m) ----
    {
        int m = tid >> 2, l4 = tid & 3;
        float s = 0.f;
#pragma unroll
        for (int lay = 0; lay < 3; ++lay) {
            const char* bh = smc + ftOff[lay];
            for (int f = l4; f < HD; f += 4) {
                float v = __bfloat162float(*(const __nv_bfloat16*)(bh + f * SB2 + m * 2))
                        + __bfloat162float(*(const __nv_bfloat16*)(bh + FT_LO + f * SB2 + m * 2));
                s = fmaf(v, wasf[lay * HD + f], s);
            }
        }
        s += __shfl_xor_sync(0xFFFFFFFFu, s, 1);
        s += __shfl_xor_sync(0xFFFFFFFFu, s, 2);
        if (l4 == 0) sdot[m] = s;
    }
    __syncthreads();
    // ---- score = tanh(A @ sdot + ba) ----
    if (tid < 64) {
        float s = 0.f;
        for (int k = 0; k < 64; ++k) s = fmaf(Af[tid * SAF + k], sdot[k], s);
        score[tid] = tanhf(s + ba[0]);
    }
    __syncthreads();
    // ---- top-K (jax tie-break: smaller index wins among equals) ----
    if (tid < 64) {
        float si = score[tid];
        int rank = 0;
#pragma unroll
        for (int j = 0; j < 64; ++j) {
            float sj = score[j];
            rank += (sj > si) || (sj == si && j < tid);
        }
        if (rank < KSEL) { int p = atomicAdd(scnt, 1); slist[p] = tid; }
    }
    __syncthreads();
    // ---- readout: mean || max of feats*score over selected (channel-major rows) ----
    for (int c = tid; c < FD; c += NT) {
        const char* bh = smc + ftOff[c >> 7] + (c & 127) * SB2;
        float ssum = 0.f, mx = -FLT_MAX;
#pragma unroll
        for (int j = 0; j < KSEL; ++j) {
            int m = slist[j];
            float v = __bfloat162float(*(const __nv_bfloat16*)(bh + m * 2))
                    + __bfloat162float(*(const __nv_bfloat16*)(bh + FT_LO + m * 2));
            v *= score[m];
            ssum += v;
            mx = fmaxf(mx, v);
        }
        rd[c]      = ssum * (1.f / (float)KSEL);
        rd[FD + c] = mx;
    }
    __syncthreads();
    // ---- MLP1: [768]->[128] ----
    {
        int j = tid & 127, q = tid >> 7;
        float a = 0.f;
        for (int c = q * 384; c < q * 384 + 384; ++c)
            a = fmaf(rd[c], M1[c * HD + j], a);
        psum[tid] = a;
        __syncthreads();
        if (tid < 128) t1[tid] = fmaxf(psum[tid] + psum[tid + 128] + c1[tid], 0.f);
    }
    __syncthreads();
    // ---- MLP2: [128]->[64] ----
    {
        int j = tid & 63, q = tid >> 6;
        float a = 0.f;
#pragma unroll
        for (int c = q * 32; c < q * 32 + 32; ++c)
            a = fmaf(t1[c], M2[c * 64 + j], a);
        psum[tid] = a;
        __syncthreads();
        if (tid < 64)
            t2[tid] = fmaxf(psum[tid] + psum[tid + 64] + psum[tid + 128] + psum[tid + 192] + c2[tid], 0.f);
    }
    __syncthreads();
    // ---- MLP3: [64]->[10] ----
    if (tid < DOUT) {
        float a = c3[tid];
#pragma unroll
        for (int c = 0; c < 64; ++c) a = fmaf(t2[c], M3[c * DOUT + tid], a);
        out[g * DOUT + tid] = a;
    }
}

extern "C" void kernel_launch(void* const* d_in, const int* in_sizes, int n_in,
                              void* d_out, int out_size)
{
    const float* x  = (const float*)d_in[0];
    const int*   ei = (const int*)d_in[1];
    // d_in[2] = batch (unused: graphs are contiguous 64-node blocks)
    const float* W1 = (const float*)d_in[3];
    const float* b1 = (const float*)d_in[4];
    const float* W2 = (const float*)d_in[5];
    const float* b2 = (const float*)d_in[6];
    const float* W3 = (const float*)d_in[7];
    const float* b3 = (const float*)d_in[8];
    const float* Wa = (const float*)d_in[9];
    const float* ba = (const float*)d_in[10];
    const float* M1 = (const float*)d_in[11];
    const float* c1 = (const float*)d_in[12];
    const float* M2 = (const float*)d_in[13];
    const float* c2 = (const float*)d_in[14];
    const float* M3 = (const float*)d_in[15];
    const float* c3 = (const float*)d_in[16];
    float* out = (float*)d_out;

    cudaFuncSetAttribute(sagpool_mma_kernel,
                         cudaFuncAttributeMaxDynamicSharedMemorySize, SMEM_BYTES);
    sagpool_mma_kernel<<<NG, NT, SMEM_BYTES>>>(x, ei, W1, b1, W2, b2, W3, b3,
                                               Wa, ba, M1, c1, M2, c2, M3, c3, out);
}